// round 15
// baseline (speedup 1.0000x reference)
#include <cuda_runtime.h>
#include <cstdint>

typedef unsigned long long u64;
typedef unsigned int u32;

#define DI __device__ __forceinline__

// ---------- packed fp32x2 helpers (Blackwell FFMA2 pipe) ----------
DI u64 dup2(float f){ u32 u = __float_as_uint(f); return ((u64)u << 32) | (u64)u; }
DI u64 fma2(u64 a, u64 b, u64 c){
    asm("fma.rn.f32x2 %0, %1, %2, %0;" : "+l"(c) : "l"(a), "l"(b));
    return c;
}
DI float lo32(u64 v){ return __uint_as_float((u32)v); }
DI float hi32(u64 v){ return __uint_as_float((u32)(v >> 32)); }
DI float gelu_f(float x){ return 0.5f * x * (1.0f + erff(x * 0.7071067811865476f)); }

// ---------- device scratch (allocation-free: __device__ globals) ----------
__device__ float g_qkv   [4096LL * 3072];        //  50 MB  (q | k | v per token)
__device__ float g_scores[32LL * 2048 * 2048];   // 512 MB  scaled q·k
__device__ float g_m     [32 * 2048];            // column max per (bh, s)
__device__ float g_linv  [32 * 2048];            // 1/sum per (bh, s)
__device__ float g_ctx   [4096LL * 1024];        // gelu(post)/sqrt(S), token-major
__device__ float g_tmp   [4096LL * 1024];        // attn out-proj (pre-LN)
__device__ float g_x     [4096LL * 1024];        // after LN1
__device__ float g_h1    [4096LL * 4096];        // gelu(lin1)
__device__ float g_y     [4096LL * 1024];        // lin2 out

// =====================================================================
// Generic NT GEMM: C[M,N] = A[M,K] * B[N,K]^T  (+bias | *scale | +bias+gelu)
// BM=BN=128, BK=16, 256 threads, 8x8 per thread, packed f32x2 accumulation.
// Batched via blockIdx.z decomposed as z1 = z/HB, z2 = z%HB with strides.
// All M,N multiples of 128 and K multiples of 16 (guaranteed by caller).
// EPI: 1 = +bias ; 2 = *scale ; 3 = +bias then gelu
// =====================================================================
template<int EPI>
__global__ __launch_bounds__(256, 2)
void gemm_nt(const float* __restrict__ Ab, const float* __restrict__ Bb,
             const float* __restrict__ bias, float* __restrict__ Cb,
             int K, int lda, int ldb, int ldc,
             long long sA1, long long sA2, long long sB1, long long sB2,
             long long sC1, long long sC2, int HB, float scale)
{
    const int z  = blockIdx.z;
    const int z1 = z / HB, z2 = z - z1 * HB;
    const float* A = Ab + z1 * sA1 + (long long)z2 * sA2;
    const float* B = Bb + z1 * sB1 + (long long)z2 * sB2;
    float*       C = Cb + z1 * sC1 + (long long)z2 * sC2;

    __shared__ u64 As2[16][129];                  // A tile, dup-packed, [k][m]
    __shared__ __align__(16) float Bs[16][130];   // B tile, [k][n]

    const int tid  = threadIdx.x;
    const long long bm = (long long)blockIdx.y * 128;
    const long long bn = (long long)blockIdx.x * 128;

    const int warp = tid >> 5, lane = tid & 31;
    const int tm = (warp >> 1) * 32 + (lane >> 3) * 8;   // 0..120
    const int tn = (warp & 1)  * 64 + (lane & 7)  * 8;   // 0..120
    const int tn2 = tn >> 1;

    // loader coords: 512 float4 per operand tile, 2 per thread
    const int lm0 = tid >> 2;          // 0..63 (and +64)
    const int lk  = (tid & 3) * 4;     // 0,4,8,12
    const float* Aload = A + (bm + lm0) * lda + lk;
    const float* Bload = B + (bn + lm0) * ldb + lk;

    float4 pa0 = *(const float4*)(Aload);
    float4 pa1 = *(const float4*)(Aload + 64LL * lda);
    float4 pb0 = *(const float4*)(Bload);
    float4 pb1 = *(const float4*)(Bload + 64LL * ldb);

    u64 acc[8][4];
    #pragma unroll
    for (int i = 0; i < 8; i++)
        #pragma unroll
        for (int j = 0; j < 4; j++) acc[i][j] = 0ULL;

    for (int k0 = 0; k0 < K; k0 += 16) {
        // commit prefetched tile to smem (A duplicated for f32x2 broadcast)
        As2[lk+0][lm0]    = dup2(pa0.x);
        As2[lk+1][lm0]    = dup2(pa0.y);
        As2[lk+2][lm0]    = dup2(pa0.z);
        As2[lk+3][lm0]    = dup2(pa0.w);
        As2[lk+0][lm0+64] = dup2(pa1.x);
        As2[lk+1][lm0+64] = dup2(pa1.y);
        As2[lk+2][lm0+64] = dup2(pa1.z);
        As2[lk+3][lm0+64] = dup2(pa1.w);
        Bs[lk+0][lm0]     = pb0.x;
        Bs[lk+1][lm0]     = pb0.y;
        Bs[lk+2][lm0]     = pb0.z;
        Bs[lk+3][lm0]     = pb0.w;
        Bs[lk+0][lm0+64]  = pb1.x;
        Bs[lk+1][lm0+64]  = pb1.y;
        Bs[lk+2][lm0+64]  = pb1.z;
        Bs[lk+3][lm0+64]  = pb1.w;
        __syncthreads();

        if (k0 + 16 < K) {  // register-prefetch next tile (overlaps compute)
            pa0 = *(const float4*)(Aload + (k0 + 16));
            pa1 = *(const float4*)(Aload + (k0 + 16) + 64LL * lda);
            pb0 = *(const float4*)(Bload + (k0 + 16));
            pb1 = *(const float4*)(Bload + (k0 + 16) + 64LL * ldb);
        }

        #pragma unroll
        for (int k = 0; k < 16; k++) {
            const u64* brow = (const u64*)(&Bs[k][0]);
            u64 ra[8], rb[4];
            #pragma unroll
            for (int i = 0; i < 8; i++) ra[i] = As2[k][tm + i];
            #pragma unroll
            for (int j = 0; j < 4; j++) rb[j] = brow[tn2 + j];
            #pragma unroll
            for (int i = 0; i < 8; i++)
                #pragma unroll
                for (int j = 0; j < 4; j++)
                    acc[i][j] = fma2(ra[i], rb[j], acc[i][j]);
        }
        __syncthreads();
    }

    #pragma unroll
    for (int i = 0; i < 8; i++) {
        float* crow = C + (bm + tm + i) * ldc + bn + tn;
        #pragma unroll
        for (int j = 0; j < 4; j++) {
            float lo = lo32(acc[i][j]);
            float hi = hi32(acc[i][j]);
            if (EPI == 1 || EPI == 3) {
                int n = (int)(bn + tn) + 2 * j;
                lo += bias[n]; hi += bias[n + 1];
            }
            if (EPI == 2) { lo *= scale; hi *= scale; }
            if (EPI == 3) { lo = gelu_f(lo); hi = gelu_f(hi); }
            *(float2*)(crow + 2 * j) = make_float2(lo, hi);
        }
    }
}

// =====================================================================
// Column softmax stats (softmax over t for each (bh, s)):
// online max + sum of exp, branchless. scores layout [z][t][s].
// =====================================================================
__global__ __launch_bounds__(256)
void softmax_stats(const float* __restrict__ S, float* __restrict__ Mv,
                   float* __restrict__ Lv)
{
    const int z = blockIdx.y;
    const int s = blockIdx.x * 256 + threadIdx.x;
    const float* p = S + (long long)z * (2048LL * 2048LL) + s;
    float m = -1e30f, l = 0.0f;
    for (int t = 0; t < 2048; t += 4) {
        float x0 = p[(long long)(t + 0) * 2048];
        float x1 = p[(long long)(t + 1) * 2048];
        float x2 = p[(long long)(t + 2) * 2048];
        float x3 = p[(long long)(t + 3) * 2048];
        float nm;
        nm = fmaxf(m, x0); l = l * __expf(m - nm) + __expf(x0 - nm); m = nm;
        nm = fmaxf(m, x1); l = l * __expf(m - nm) + __expf(x1 - nm); m = nm;
        nm = fmaxf(m, x2); l = l * __expf(m - nm) + __expf(x2 - nm); m = nm;
        nm = fmaxf(m, x3); l = l * __expf(m - nm) + __expf(x3 - nm); m = nm;
    }
    Mv[z * 2048 + s] = m;
    Lv[z * 2048 + s] = 1.0f / l;
}

// =====================================================================
// post[t,d] = sum_s exp(score[t,s]-m[s])*invl[s] * V[s,d]; epilogue
// gelu(x)/sqrt(S) scattered into ctx[token][h*64+d].
// BM=128, BN=64(=head_dim), BK=16, 256 threads, 8x4 per thread.
// =====================================================================
__global__ __launch_bounds__(256, 2)
void gemm_attnv(const float* __restrict__ Sc, const float* __restrict__ QKV,
                const float* __restrict__ Mv, const float* __restrict__ Lv,
                float* __restrict__ Ctx)
{
    const int z = blockIdx.z;
    const int b = z >> 4, h = z & 15;
    const float* A  = Sc  + (long long)z * (2048LL * 2048LL);
    const float* V  = QKV + (long long)b * (2048LL * 3072LL) + 2048 + h * 64;
    const float* mv = Mv + z * 2048;
    const float* lv = Lv + z * 2048;
    float*       C  = Ctx + (long long)b * (2048LL * 1024LL) + h * 64;

    __shared__ u64 As2[16][129];
    __shared__ __align__(16) float Bs[16][68];

    const int tid = threadIdx.x;
    const long long bm = (long long)blockIdx.y * 128;

    const int warp = tid >> 5, lane = tid & 31;
    const int tm = (warp >> 1) * 32 + (lane >> 3) * 8;   // 0..120
    const int tn = (warp & 1)  * 32 + (lane & 7)  * 4;   // 0..60
    const int tn2 = tn >> 1;

    const int lm0 = tid >> 2;
    const int lk  = (tid & 3) * 4;
    const float* Aload = A + (bm + lm0) * 2048 + lk;
    const int vRow = tid >> 4;              // 0..15
    const int vCol = (tid & 15) * 4;        // 0..60
    const float* Vload = V + (long long)vRow * 3072 + vCol;

    float4 pa0 = *(const float4*)(Aload);
    float4 pa1 = *(const float4*)(Aload + 64LL * 2048);
    float4 pm  = *(const float4*)(mv + lk);
    float4 pl  = *(const float4*)(lv + lk);
    float4 pv  = *(const float4*)(Vload);

    u64 acc[8][2];
    #pragma unroll
    for (int i = 0; i < 8; i++) { acc[i][0] = 0ULL; acc[i][1] = 0ULL; }

    for (int k0 = 0; k0 < 2048; k0 += 16) {
        As2[lk+0][lm0]    = dup2(__expf(pa0.x - pm.x) * pl.x);
        As2[lk+1][lm0]    = dup2(__expf(pa0.y - pm.y) * pl.y);
        As2[lk+2][lm0]    = dup2(__expf(pa0.z - pm.z) * pl.z);
        As2[lk+3][lm0]    = dup2(__expf(pa0.w - pm.w) * pl.w);
        As2[lk+0][lm0+64] = dup2(__expf(pa1.x - pm.x) * pl.x);
        As2[lk+1][lm0+64] = dup2(__expf(pa1.y - pm.y) * pl.y);
        As2[lk+2][lm0+64] = dup2(__expf(pa1.z - pm.z) * pl.z);
        As2[lk+3][lm0+64] = dup2(__expf(pa1.w - pm.w) * pl.w);
        *(float4*)(&Bs[vRow][vCol]) = pv;
        __syncthreads();

        if (k0 + 16 < 2048) {
            pa0 = *(const float4*)(Aload + (k0 + 16));
            pa1 = *(const float4*)(Aload + (k0 + 16) + 64LL * 2048);
            pm  = *(const float4*)(mv + (k0 + 16) + lk);
            pl  = *(const float4*)(lv + (k0 + 16) + lk);
            pv  = *(const float4*)(Vload + (long long)(k0 + 16) * 3072);
        }

        #pragma unroll
        for (int k = 0; k < 16; k++) {
            const u64* brow = (const u64*)(&Bs[k][0]);
            u64 ra[8];
            #pragma unroll
            for (int i = 0; i < 8; i++) ra[i] = As2[k][tm + i];
            u64 rb0 = brow[tn2], rb1 = brow[tn2 + 1];
            #pragma unroll
            for (int i = 0; i < 8; i++) {
                acc[i][0] = fma2(ra[i], rb0, acc[i][0]);
                acc[i][1] = fma2(ra[i], rb1, acc[i][1]);
            }
        }
        __syncthreads();
    }

    const float rs = 0.022097086912079608f;  // 1/sqrt(2048)
    #pragma unroll
    for (int i = 0; i < 8; i++) {
        float* crow = C + (bm + tm + i) * 1024 + tn;
        #pragma unroll
        for (int j = 0; j < 2; j++) {
            float lo = gelu_f(lo32(acc[i][j])) * rs;
            float hi = gelu_f(hi32(acc[i][j])) * rs;
            *(float2*)(crow + 2 * j) = make_float2(lo, hi);
        }
    }
}

// =====================================================================
// LayerNorm(x + y) * g + b   (row = 1024, one block per token row)
// =====================================================================
__global__ __launch_bounds__(256)
void ln_kernel(const float* __restrict__ X, const float* __restrict__ Y,
               const float* __restrict__ g, const float* __restrict__ be,
               float* __restrict__ O)
{
    const long long row = blockIdx.x;
    const int t = threadIdx.x;
    const float4 a = *(const float4*)(X + row * 1024 + t * 4);
    const float4 c = *(const float4*)(Y + row * 1024 + t * 4);
    float v0 = a.x + c.x, v1 = a.y + c.y, v2 = a.z + c.z, v3 = a.w + c.w;
    float s = v0 + v1 + v2 + v3;
    float q = v0 * v0 + v1 * v1 + v2 * v2 + v3 * v3;
    #pragma unroll
    for (int o = 16; o > 0; o >>= 1) {
        s += __shfl_xor_sync(0xffffffffu, s, o);
        q += __shfl_xor_sync(0xffffffffu, q, o);
    }
    __shared__ float ss[8], qq[8];
    const int w = t >> 5;
    if ((t & 31) == 0) { ss[w] = s; qq[w] = q; }
    __syncthreads();
    if (t < 32) {
        s = (t < 8) ? ss[t] : 0.0f;
        q = (t < 8) ? qq[t] : 0.0f;
        #pragma unroll
        for (int o = 4; o > 0; o >>= 1) {
            s += __shfl_xor_sync(0xffffffffu, s, o);
            q += __shfl_xor_sync(0xffffffffu, q, o);
        }
        if (t == 0) { ss[0] = s; qq[0] = q; }
    }
    __syncthreads();
    const float mu  = ss[0] * (1.0f / 1024.0f);
    const float var = qq[0] * (1.0f / 1024.0f) - mu * mu;
    const float r   = rsqrtf(var + 1e-5f);
    const float4 gg = *(const float4*)(g  + t * 4);
    const float4 bb = *(const float4*)(be + t * 4);
    float4 o4;
    o4.x = (v0 - mu) * r * gg.x + bb.x;
    o4.y = (v1 - mu) * r * gg.y + bb.y;
    o4.z = (v2 - mu) * r * gg.z + bb.z;
    o4.w = (v3 - mu) * r * gg.w + bb.w;
    *(float4*)(O + row * 1024 + t * 4) = o4;
}

// =====================================================================
// Host launcher (graph-capturable: kernel launches only)
// =====================================================================
extern "C" void kernel_launch(void* const* d_in, const int* in_sizes, int n_in,
                              void* d_out, int out_size)
{
    (void)in_sizes; (void)n_in; (void)out_size;
    const float* src  = (const float*)d_in[0];
    const float* ipw  = (const float*)d_in[1];
    const float* ipb  = (const float*)d_in[2];
    const float* outw = (const float*)d_in[3];
    const float* outb = (const float*)d_in[4];
    const float* l1w  = (const float*)d_in[5];
    const float* l1b  = (const float*)d_in[6];
    const float* l2w  = (const float*)d_in[7];
    const float* l2b  = (const float*)d_in[8];
    const float* g1   = (const float*)d_in[9];
    const float* b1   = (const float*)d_in[10];
    const float* g2   = (const float*)d_in[11];
    const float* b2   = (const float*)d_in[12];
    float* out = (float*)d_out;

    float *qkv, *sc, *mv, *lv, *ctx, *tmp, *x, *h1, *y;
    cudaGetSymbolAddress((void**)&qkv, g_qkv);
    cudaGetSymbolAddress((void**)&sc,  g_scores);
    cudaGetSymbolAddress((void**)&mv,  g_m);
    cudaGetSymbolAddress((void**)&lv,  g_linv);
    cudaGetSymbolAddress((void**)&ctx, g_ctx);
    cudaGetSymbolAddress((void**)&tmp, g_tmp);
    cudaGetSymbolAddress((void**)&x,   g_x);
    cudaGetSymbolAddress((void**)&h1,  g_h1);
    cudaGetSymbolAddress((void**)&y,   g_y);

    const dim3 T(256);

    // 1) qkv = src @ in_proj_w^T + in_proj_b     [4096, 3072]
    gemm_nt<1><<<dim3(24, 32, 1), T>>>(src, ipw, ipb, qkv,
        1024, 1024, 1024, 3072, 0, 0, 0, 0, 0, 0, 1, 1.0f);

    // 2) scores[bh][t][s] = (q_t . k_s) * 1/sqrt(64)   batched over 32 (b,h)
    gemm_nt<2><<<dim3(16, 16, 32), T>>>(qkv, qkv + 1024, nullptr, sc,
        64, 3072, 3072, 2048,
        6291456LL, 64LL,          // A: +b*2048*3072, +h*64
        6291456LL, 64LL,          // B: same (k base already +1024)
        67108864LL, 4194304LL,    // C: +b*16*2048^2, +h*2048^2
        16, 0.125f);

    // 3) column-softmax stats over t
    softmax_stats<<<dim3(8, 32), T>>>(sc, mv, lv);

    // 4) post = softmaxed(scores)^applied . V, gelu, /sqrt(S) -> ctx
    gemm_attnv<<<dim3(1, 16, 32), T>>>(sc, qkv, mv, lv, ctx);

    // 5) tmp = ctx @ out_w^T + out_b
    gemm_nt<1><<<dim3(8, 32, 1), T>>>(ctx, outw, outb, tmp,
        1024, 1024, 1024, 1024, 0, 0, 0, 0, 0, 0, 1, 1.0f);

    // 6) x = LN(src + tmp)
    ln_kernel<<<4096, T>>>(src, tmp, g1, b1, x);

    // 7) h1 = gelu(x @ lin1_w^T + lin1_b)        [4096, 4096]
    gemm_nt<3><<<dim3(32, 32, 1), T>>>(x, l1w, l1b, h1,
        1024, 1024, 1024, 4096, 0, 0, 0, 0, 0, 0, 1, 1.0f);

    // 8) y = h1 @ lin2_w^T + lin2_b              [4096, 1024]
    gemm_nt<1><<<dim3(8, 32, 1), T>>>(h1, l2w, l2b, y,
        4096, 4096, 4096, 1024, 0, 0, 0, 0, 0, 0, 1, 1.0f);

    // 9) out = LN(x + y)
    ln_kernel<<<4096, T>>>(x, y, g2, b2, out);
}

// round 16
// speedup vs baseline: 1.0014x; 1.0014x over previous
#include <cuda_runtime.h>
#include <cstdint>

typedef unsigned long long u64;
typedef unsigned int u32;

#define DI __device__ __forceinline__

// ---------- packed fp32x2 helpers (Blackwell FFMA2 pipe) ----------
DI u64 dup2(float f){ u32 u = __float_as_uint(f); return ((u64)u << 32) | (u64)u; }
DI u64 fma2(u64 a, u64 b, u64 c){
    asm("fma.rn.f32x2 %0, %1, %2, %0;" : "+l"(c) : "l"(a), "l"(b));
    return c;
}
DI float lo32(u64 v){ return __uint_as_float((u32)v); }
DI float hi32(u64 v){ return __uint_as_float((u32)(v >> 32)); }
DI float gelu_f(float x){ return 0.5f * x * (1.0f + erff(x * 0.7071067811865476f)); }

// ---------- device scratch (allocation-free: __device__ globals) ----------
__device__ float g_qkv   [4096LL * 3072];        //  50 MB  (q | k | v per token)
__device__ float g_scores[32LL * 2048 * 2048];   // 512 MB  scaled q·k
__device__ float g_m     [32 * 2048];            // column max per (bh, s)
__device__ float g_linv  [32 * 2048];            // 1/sum per (bh, s)
__device__ float g_ctx   [4096LL * 1024];        // gelu(post)/sqrt(S), token-major
__device__ float g_tmp   [4096LL * 1024];        // attn out-proj (pre-LN)
__device__ float g_x     [4096LL * 1024];        // after LN1
__device__ float g_h1    [4096LL * 4096];        // gelu(lin1)
__device__ float g_y     [4096LL * 1024];        // lin2 out

// =====================================================================
// Generic NT GEMM: C[M,N] = A[M,K] * B[N,K]^T  (+bias | *scale | +bias+gelu)
// BM=BN=128, BK=16, 256 threads, 8x8 per thread, packed f32x2 accumulation.
// Batched via blockIdx.z decomposed as z1 = z/HB, z2 = z%HB with strides.
// All M,N multiples of 128 and K multiples of 16 (guaranteed by caller).
// EPI: 1 = +bias ; 2 = *scale ; 3 = +bias then gelu
// =====================================================================
template<int EPI>
__global__ __launch_bounds__(256, 2)
void gemm_nt(const float* __restrict__ Ab, const float* __restrict__ Bb,
             const float* __restrict__ bias, float* __restrict__ Cb,
             int K, int lda, int ldb, int ldc,
             long long sA1, long long sA2, long long sB1, long long sB2,
             long long sC1, long long sC2, int HB, float scale)
{
    const int z  = blockIdx.z;
    const int z1 = z / HB, z2 = z - z1 * HB;
    const float* A = Ab + z1 * sA1 + (long long)z2 * sA2;
    const float* B = Bb + z1 * sB1 + (long long)z2 * sB2;
    float*       C = Cb + z1 * sC1 + (long long)z2 * sC2;

    __shared__ u64 As2[16][129];                  // A tile, dup-packed, [k][m]
    __shared__ __align__(16) float Bs[16][130];   // B tile, [k][n]

    const int tid  = threadIdx.x;
    const long long bm = (long long)blockIdx.y * 128;
    const long long bn = (long long)blockIdx.x * 128;

    const int warp = tid >> 5, lane = tid & 31;
    const int tm = (warp >> 1) * 32 + (lane >> 3) * 8;   // 0..120
    const int tn = (warp & 1)  * 64 + (lane & 7)  * 8;   // 0..120
    const int tn2 = tn >> 1;

    // loader coords: 512 float4 per operand tile, 2 per thread
    const int lm0 = tid >> 2;          // 0..63 (and +64)
    const int lk  = (tid & 3) * 4;     // 0,4,8,12
    const float* Aload = A + (bm + lm0) * lda + lk;
    const float* Bload = B + (bn + lm0) * ldb + lk;

    float4 pa0 = *(const float4*)(Aload);
    float4 pa1 = *(const float4*)(Aload + 64LL * lda);
    float4 pb0 = *(const float4*)(Bload);
    float4 pb1 = *(const float4*)(Bload + 64LL * ldb);

    u64 acc[8][4];
    #pragma unroll
    for (int i = 0; i < 8; i++)
        #pragma unroll
        for (int j = 0; j < 4; j++) acc[i][j] = 0ULL;

    for (int k0 = 0; k0 < K; k0 += 16) {
        // commit prefetched tile to smem (A duplicated for f32x2 broadcast)
        As2[lk+0][lm0]    = dup2(pa0.x);
        As2[lk+1][lm0]    = dup2(pa0.y);
        As2[lk+2][lm0]    = dup2(pa0.z);
        As2[lk+3][lm0]    = dup2(pa0.w);
        As2[lk+0][lm0+64] = dup2(pa1.x);
        As2[lk+1][lm0+64] = dup2(pa1.y);
        As2[lk+2][lm0+64] = dup2(pa1.z);
        As2[lk+3][lm0+64] = dup2(pa1.w);
        Bs[lk+0][lm0]     = pb0.x;
        Bs[lk+1][lm0]     = pb0.y;
        Bs[lk+2][lm0]     = pb0.z;
        Bs[lk+3][lm0]     = pb0.w;
        Bs[lk+0][lm0+64]  = pb1.x;
        Bs[lk+1][lm0+64]  = pb1.y;
        Bs[lk+2][lm0+64]  = pb1.z;
        Bs[lk+3][lm0+64]  = pb1.w;
        __syncthreads();

        if (k0 + 16 < K) {  // register-prefetch next tile (overlaps compute)
            pa0 = *(const float4*)(Aload + (k0 + 16));
            pa1 = *(const float4*)(Aload + (k0 + 16) + 64LL * lda);
            pb0 = *(const float4*)(Bload + (k0 + 16));
            pb1 = *(const float4*)(Bload + (k0 + 16) + 64LL * ldb);
        }

        #pragma unroll
        for (int k = 0; k < 16; k++) {
            const u64* brow = (const u64*)(&Bs[k][0]);
            u64 ra[8], rb[4];
            #pragma unroll
            for (int i = 0; i < 8; i++) ra[i] = As2[k][tm + i];
            #pragma unroll
            for (int j = 0; j < 4; j++) rb[j] = brow[tn2 + j];
            #pragma unroll
            for (int i = 0; i < 8; i++)
                #pragma unroll
                for (int j = 0; j < 4; j++)
                    acc[i][j] = fma2(ra[i], rb[j], acc[i][j]);
        }
        __syncthreads();
    }

    #pragma unroll
    for (int i = 0; i < 8; i++) {
        float* crow = C + (bm + tm + i) * ldc + bn + tn;
        #pragma unroll
        for (int j = 0; j < 4; j++) {
            float lo = lo32(acc[i][j]);
            float hi = hi32(acc[i][j]);
            if (EPI == 1 || EPI == 3) {
                int n = (int)(bn + tn) + 2 * j;
                lo += bias[n]; hi += bias[n + 1];
            }
            if (EPI == 2) { lo *= scale; hi *= scale; }
            if (EPI == 3) { lo = gelu_f(lo); hi = gelu_f(hi); }
            *(float2*)(crow + 2 * j) = make_float2(lo, hi);
        }
    }
}

// =====================================================================
// Column softmax stats (softmax over t for each (bh, s)):
// online max + sum of exp, branchless. scores layout [z][t][s].
// =====================================================================
__global__ __launch_bounds__(256)
void softmax_stats(const float* __restrict__ S, float* __restrict__ Mv,
                   float* __restrict__ Lv)
{
    const int z = blockIdx.y;
    const int s = blockIdx.x * 256 + threadIdx.x;
    const float* p = S + (long long)z * (2048LL * 2048LL) + s;
    float m = -1e30f, l = 0.0f;
    for (int t = 0; t < 2048; t += 4) {
        float x0 = p[(long long)(t + 0) * 2048];
        float x1 = p[(long long)(t + 1) * 2048];
        float x2 = p[(long long)(t + 2) * 2048];
        float x3 = p[(long long)(t + 3) * 2048];
        float nm;
        nm = fmaxf(m, x0); l = l * __expf(m - nm) + __expf(x0 - nm); m = nm;
        nm = fmaxf(m, x1); l = l * __expf(m - nm) + __expf(x1 - nm); m = nm;
        nm = fmaxf(m, x2); l = l * __expf(m - nm) + __expf(x2 - nm); m = nm;
        nm = fmaxf(m, x3); l = l * __expf(m - nm) + __expf(x3 - nm); m = nm;
    }
    Mv[z * 2048 + s] = m;
    Lv[z * 2048 + s] = 1.0f / l;
}

// =====================================================================
// post[t,d] = sum_s exp(score[t,s]-m[s])*invl[s] * V[s,d]; epilogue
// gelu(x)/sqrt(S) scattered into ctx[token][h*64+d].
// BM=128, BN=64(=head_dim), BK=16, 256 threads, 8x4 per thread.
// =====================================================================
__global__ __launch_bounds__(256, 2)
void gemm_attnv(const float* __restrict__ Sc, const float* __restrict__ QKV,
                const float* __restrict__ Mv, const float* __restrict__ Lv,
                float* __restrict__ Ctx)
{
    const int z = blockIdx.z;
    const int b = z >> 4, h = z & 15;
    const float* A  = Sc  + (long long)z * (2048LL * 2048LL);
    const float* V  = QKV + (long long)b * (2048LL * 3072LL) + 2048 + h * 64;
    const float* mv = Mv + z * 2048;
    const float* lv = Lv + z * 2048;
    float*       C  = Ctx + (long long)b * (2048LL * 1024LL) + h * 64;

    __shared__ u64 As2[16][129];
    __shared__ __align__(16) float Bs[16][68];

    const int tid = threadIdx.x;
    const long long bm = (long long)blockIdx.y * 128;

    const int warp = tid >> 5, lane = tid & 31;
    const int tm = (warp >> 1) * 32 + (lane >> 3) * 8;   // 0..120
    const int tn = (warp & 1)  * 32 + (lane & 7)  * 4;   // 0..60
    const int tn2 = tn >> 1;

    const int lm0 = tid >> 2;
    const int lk  = (tid & 3) * 4;
    const float* Aload = A + (bm + lm0) * 2048 + lk;
    const int vRow = tid >> 4;              // 0..15
    const int vCol = (tid & 15) * 4;        // 0..60
    const float* Vload = V + (long long)vRow * 3072 + vCol;

    float4 pa0 = *(const float4*)(Aload);
    float4 pa1 = *(const float4*)(Aload + 64LL * 2048);
    float4 pm  = *(const float4*)(mv + lk);
    float4 pl  = *(const float4*)(lv + lk);
    float4 pv  = *(const float4*)(Vload);

    u64 acc[8][2];
    #pragma unroll
    for (int i = 0; i < 8; i++) { acc[i][0] = 0ULL; acc[i][1] = 0ULL; }

    for (int k0 = 0; k0 < 2048; k0 += 16) {
        As2[lk+0][lm0]    = dup2(__expf(pa0.x - pm.x) * pl.x);
        As2[lk+1][lm0]    = dup2(__expf(pa0.y - pm.y) * pl.y);
        As2[lk+2][lm0]    = dup2(__expf(pa0.z - pm.z) * pl.z);
        As2[lk+3][lm0]    = dup2(__expf(pa0.w - pm.w) * pl.w);
        As2[lk+0][lm0+64] = dup2(__expf(pa1.x - pm.x) * pl.x);
        As2[lk+1][lm0+64] = dup2(__expf(pa1.y - pm.y) * pl.y);
        As2[lk+2][lm0+64] = dup2(__expf(pa1.z - pm.z) * pl.z);
        As2[lk+3][lm0+64] = dup2(__expf(pa1.w - pm.w) * pl.w);
        *(float4*)(&Bs[vRow][vCol]) = pv;
        __syncthreads();

        if (k0 + 16 < 2048) {
            pa0 = *(const float4*)(Aload + (k0 + 16));
            pa1 = *(const float4*)(Aload + (k0 + 16) + 64LL * 2048);
            pm  = *(const float4*)(mv + (k0 + 16) + lk);
            pl  = *(const float4*)(lv + (k0 + 16) + lk);
            pv  = *(const float4*)(Vload + (long long)(k0 + 16) * 3072);
        }

        #pragma unroll
        for (int k = 0; k < 16; k++) {
            const u64* brow = (const u64*)(&Bs[k][0]);
            u64 ra[8];
            #pragma unroll
            for (int i = 0; i < 8; i++) ra[i] = As2[k][tm + i];
            u64 rb0 = brow[tn2], rb1 = brow[tn2 + 1];
            #pragma unroll
            for (int i = 0; i < 8; i++) {
                acc[i][0] = fma2(ra[i], rb0, acc[i][0]);
                acc[i][1] = fma2(ra[i], rb1, acc[i][1]);
            }
        }
        __syncthreads();
    }

    const float rs = 0.022097086912079608f;  // 1/sqrt(2048)
    #pragma unroll
    for (int i = 0; i < 8; i++) {
        float* crow = C + (bm + tm + i) * 1024 + tn;
        #pragma unroll
        for (int j = 0; j < 2; j++) {
            float lo = gelu_f(lo32(acc[i][j])) * rs;
            float hi = gelu_f(hi32(acc[i][j])) * rs;
            *(float2*)(crow + 2 * j) = make_float2(lo, hi);
        }
    }
}

// =====================================================================
// LayerNorm(x + y) * g + b   (row = 1024, one block per token row)
// =====================================================================
__global__ __launch_bounds__(256)
void ln_kernel(const float* __restrict__ X, const float* __restrict__ Y,
               const float* __restrict__ g, const float* __restrict__ be,
               float* __restrict__ O)
{
    const long long row = blockIdx.x;
    const int t = threadIdx.x;
    const float4 a = *(const float4*)(X + row * 1024 + t * 4);
    const float4 c = *(const float4*)(Y + row * 1024 + t * 4);
    float v0 = a.x + c.x, v1 = a.y + c.y, v2 = a.z + c.z, v3 = a.w + c.w;
    float s = v0 + v1 + v2 + v3;
    float q = v0 * v0 + v1 * v1 + v2 * v2 + v3 * v3;
    #pragma unroll
    for (int o = 16; o > 0; o >>= 1) {
        s += __shfl_xor_sync(0xffffffffu, s, o);
        q += __shfl_xor_sync(0xffffffffu, q, o);
    }
    __shared__ float ss[8], qq[8];
    const int w = t >> 5;
    if ((t & 31) == 0) { ss[w] = s; qq[w] = q; }
    __syncthreads();
    if (t < 32) {
        s = (t < 8) ? ss[t] : 0.0f;
        q = (t < 8) ? qq[t] : 0.0f;
        #pragma unroll
        for (int o = 4; o > 0; o >>= 1) {
            s += __shfl_xor_sync(0xffffffffu, s, o);
            q += __shfl_xor_sync(0xffffffffu, q, o);
        }
        if (t == 0) { ss[0] = s; qq[0] = q; }
    }
    __syncthreads();
    const float mu  = ss[0] * (1.0f / 1024.0f);
    const float var = qq[0] * (1.0f / 1024.0f) - mu * mu;
    const float r   = rsqrtf(var + 1e-5f);
    const float4 gg = *(const float4*)(g  + t * 4);
    const float4 bb = *(const float4*)(be + t * 4);
    float4 o4;
    o4.x = (v0 - mu) * r * gg.x + bb.x;
    o4.y = (v1 - mu) * r * gg.y + bb.y;
    o4.z = (v2 - mu) * r * gg.z + bb.z;
    o4.w = (v3 - mu) * r * gg.w + bb.w;
    *(float4*)(O + row * 1024 + t * 4) = o4;
}

// =====================================================================
// Host launcher (graph-capturable: kernel launches only)
// =====================================================================
extern "C" void kernel_launch(void* const* d_in, const int* in_sizes, int n_in,
                              void* d_out, int out_size)
{
    (void)in_sizes; (void)n_in; (void)out_size;
    const float* src  = (const float*)d_in[0];
    const float* ipw  = (const float*)d_in[1];
    const float* ipb  = (const float*)d_in[2];
    const float* outw = (const float*)d_in[3];
    const float* outb = (const float*)d_in[4];
    const float* l1w  = (const float*)d_in[5];
    const float* l1b  = (const float*)d_in[6];
    const float* l2w  = (const float*)d_in[7];
    const float* l2b  = (const float*)d_in[8];
    const float* g1   = (const float*)d_in[9];
    const float* b1   = (const float*)d_in[10];
    const float* g2   = (const float*)d_in[11];
    const float* b2   = (const float*)d_in[12];
    float* out = (float*)d_out;

    float *qkv, *sc, *mv, *lv, *ctx, *tmp, *x, *h1, *y;
    cudaGetSymbolAddress((void**)&qkv, g_qkv);
    cudaGetSymbolAddress((void**)&sc,  g_scores);
    cudaGetSymbolAddress((void**)&mv,  g_m);
    cudaGetSymbolAddress((void**)&lv,  g_linv);
    cudaGetSymbolAddress((void**)&ctx, g_ctx);
    cudaGetSymbolAddress((void**)&tmp, g_tmp);
    cudaGetSymbolAddress((void**)&x,   g_x);
    cudaGetSymbolAddress((void**)&h1,  g_h1);
    cudaGetSymbolAddress((void**)&y,   g_y);

    const dim3 T(256);

    // 1) qkv = src @ in_proj_w^T + in_proj_b     [4096, 3072]
    gemm_nt<1><<<dim3(24, 32, 1), T>>>(src, ipw, ipb, qkv,
        1024, 1024, 1024, 3072, 0, 0, 0, 0, 0, 0, 1, 1.0f);

    // 2) scores[bh][t][s] = (q_t . k_s) * 1/sqrt(64)   batched over 32 (b,h)
    gemm_nt<2><<<dim3(16, 16, 32), T>>>(qkv, qkv + 1024, nullptr, sc,
        64, 3072, 3072, 2048,
        6291456LL, 64LL,          // A: +b*2048*3072, +h*64
        6291456LL, 64LL,          // B: same (k base already +1024)
        67108864LL, 4194304LL,    // C: +b*16*2048^2, +h*2048^2
        16, 0.125f);

    // 3) column-softmax stats over t
    softmax_stats<<<dim3(8, 32), T>>>(sc, mv, lv);

    // 4) post = softmaxed(scores)^applied . V, gelu, /sqrt(S) -> ctx
    gemm_attnv<<<dim3(1, 16, 32), T>>>(sc, qkv, mv, lv, ctx);

    // 5) tmp = ctx @ out_w^T + out_b
    gemm_nt<1><<<dim3(8, 32, 1), T>>>(ctx, outw, outb, tmp,
        1024, 1024, 1024, 1024, 0, 0, 0, 0, 0, 0, 1, 1.0f);

    // 6) x = LN(src + tmp)
    ln_kernel<<<4096, T>>>(src, tmp, g1, b1, x);

    // 7) h1 = gelu(x @ lin1_w^T + lin1_b)        [4096, 4096]
    gemm_nt<3><<<dim3(32, 32, 1), T>>>(x, l1w, l1b, h1,
        1024, 1024, 1024, 4096, 0, 0, 0, 0, 0, 0, 1, 1.0f);

    // 8) y = h1 @ lin2_w^T + lin2_b              [4096, 1024]
    gemm_nt<1><<<dim3(8, 32, 1), T>>>(h1, l2w, l2b, y,
        4096, 4096, 4096, 1024, 0, 0, 0, 0, 0, 0, 1, 1.0f);

    // 9) out = LN(x + y)
    ln_kernel<<<4096, T>>>(x, y, g2, b2, out);
}

// round 17
// speedup vs baseline: 1.0016x; 1.0002x over previous
#include <cuda_runtime.h>
#include <cstdint>

typedef unsigned long long u64;
typedef unsigned int u32;

#define DI __device__ __forceinline__

// ---------- packed fp32x2 helpers (Blackwell FFMA2 pipe) ----------
DI u64 dup2(float f){ u32 u = __float_as_uint(f); return ((u64)u << 32) | (u64)u; }
DI u64 fma2(u64 a, u64 b, u64 c){
    asm("fma.rn.f32x2 %0, %1, %2, %0;" : "+l"(c) : "l"(a), "l"(b));
    return c;
}
DI float lo32(u64 v){ return __uint_as_float((u32)v); }
DI float hi32(u64 v){ return __uint_as_float((u32)(v >> 32)); }
DI float gelu_f(float x){ return 0.5f * x * (1.0f + erff(x * 0.7071067811865476f)); }

// ---------- device scratch (allocation-free: __device__ globals) ----------
__device__ float g_qkv   [4096LL * 3072];        //  50 MB  (q | k | v per token)
__device__ float g_scores[32LL * 2048 * 2048];   // 512 MB  scaled q·k
__device__ float g_m     [32 * 2048];            // column max per (bh, s)
__device__ float g_linv  [32 * 2048];            // 1/sum per (bh, s)
__device__ float g_ctx   [4096LL * 1024];        // gelu(post)/sqrt(S), token-major
__device__ float g_tmp   [4096LL * 1024];        // attn out-proj (pre-LN)
__device__ float g_x     [4096LL * 1024];        // after LN1
__device__ float g_h1    [4096LL * 4096];        // gelu(lin1)
__device__ float g_y     [4096LL * 1024];        // lin2 out

// =====================================================================
// Generic NT GEMM: C[M,N] = A[M,K] * B[N,K]^T  (+bias | *scale | +bias+gelu)
// BM=BN=128, BK=16, 256 threads, 8x8 per thread, packed f32x2 accumulation.
// Batched via blockIdx.z decomposed as z1 = z/HB, z2 = z%HB with strides.
// All M,N multiples of 128 and K multiples of 16 (guaranteed by caller).
// EPI: 1 = +bias ; 2 = *scale ; 3 = +bias then gelu
// =====================================================================
template<int EPI>
__global__ __launch_bounds__(256, 2)
void gemm_nt(const float* __restrict__ Ab, const float* __restrict__ Bb,
             const float* __restrict__ bias, float* __restrict__ Cb,
             int K, int lda, int ldb, int ldc,
             long long sA1, long long sA2, long long sB1, long long sB2,
             long long sC1, long long sC2, int HB, float scale)
{
    const int z  = blockIdx.z;
    const int z1 = z / HB, z2 = z - z1 * HB;
    const float* A = Ab + z1 * sA1 + (long long)z2 * sA2;
    const float* B = Bb + z1 * sB1 + (long long)z2 * sB2;
    float*       C = Cb + z1 * sC1 + (long long)z2 * sC2;

    __shared__ u64 As2[16][129];                  // A tile, dup-packed, [k][m]
    __shared__ __align__(16) float Bs[16][130];   // B tile, [k][n]

    const int tid  = threadIdx.x;
    const long long bm = (long long)blockIdx.y * 128;
    const long long bn = (long long)blockIdx.x * 128;

    const int warp = tid >> 5, lane = tid & 31;
    const int tm = (warp >> 1) * 32 + (lane >> 3) * 8;   // 0..120
    const int tn = (warp & 1)  * 64 + (lane & 7)  * 8;   // 0..120
    const int tn2 = tn >> 1;

    // loader coords: 512 float4 per operand tile, 2 per thread
    const int lm0 = tid >> 2;          // 0..63 (and +64)
    const int lk  = (tid & 3) * 4;     // 0,4,8,12
    const float* Aload = A + (bm + lm0) * lda + lk;
    const float* Bload = B + (bn + lm0) * ldb + lk;

    float4 pa0 = *(const float4*)(Aload);
    float4 pa1 = *(const float4*)(Aload + 64LL * lda);
    float4 pb0 = *(const float4*)(Bload);
    float4 pb1 = *(const float4*)(Bload + 64LL * ldb);

    u64 acc[8][4];
    #pragma unroll
    for (int i = 0; i < 8; i++)
        #pragma unroll
        for (int j = 0; j < 4; j++) acc[i][j] = 0ULL;

    for (int k0 = 0; k0 < K; k0 += 16) {
        // commit prefetched tile to smem (A duplicated for f32x2 broadcast)
        As2[lk+0][lm0]    = dup2(pa0.x);
        As2[lk+1][lm0]    = dup2(pa0.y);
        As2[lk+2][lm0]    = dup2(pa0.z);
        As2[lk+3][lm0]    = dup2(pa0.w);
        As2[lk+0][lm0+64] = dup2(pa1.x);
        As2[lk+1][lm0+64] = dup2(pa1.y);
        As2[lk+2][lm0+64] = dup2(pa1.z);
        As2[lk+3][lm0+64] = dup2(pa1.w);
        Bs[lk+0][lm0]     = pb0.x;
        Bs[lk+1][lm0]     = pb0.y;
        Bs[lk+2][lm0]     = pb0.z;
        Bs[lk+3][lm0]     = pb0.w;
        Bs[lk+0][lm0+64]  = pb1.x;
        Bs[lk+1][lm0+64]  = pb1.y;
        Bs[lk+2][lm0+64]  = pb1.z;
        Bs[lk+3][lm0+64]  = pb1.w;
        __syncthreads();

        if (k0 + 16 < K) {  // register-prefetch next tile (overlaps compute)
            pa0 = *(const float4*)(Aload + (k0 + 16));
            pa1 = *(const float4*)(Aload + (k0 + 16) + 64LL * lda);
            pb0 = *(const float4*)(Bload + (k0 + 16));
            pb1 = *(const float4*)(Bload + (k0 + 16) + 64LL * ldb);
        }

        #pragma unroll
        for (int k = 0; k < 16; k++) {
            const u64* brow = (const u64*)(&Bs[k][0]);
            u64 ra[8], rb[4];
            #pragma unroll
            for (int i = 0; i < 8; i++) ra[i] = As2[k][tm + i];
            #pragma unroll
            for (int j = 0; j < 4; j++) rb[j] = brow[tn2 + j];
            #pragma unroll
            for (int i = 0; i < 8; i++)
                #pragma unroll
                for (int j = 0; j < 4; j++)
                    acc[i][j] = fma2(ra[i], rb[j], acc[i][j]);
        }
        __syncthreads();
    }

    #pragma unroll
    for (int i = 0; i < 8; i++) {
        float* crow = C + (bm + tm + i) * ldc + bn + tn;
        #pragma unroll
        for (int j = 0; j < 4; j++) {
            float lo = lo32(acc[i][j]);
            float hi = hi32(acc[i][j]);
            if (EPI == 1 || EPI == 3) {
                int n = (int)(bn + tn) + 2 * j;
                lo += bias[n]; hi += bias[n + 1];
            }
            if (EPI == 2) { lo *= scale; hi *= scale; }
            if (EPI == 3) { lo = gelu_f(lo); hi = gelu_f(hi); }
            *(float2*)(crow + 2 * j) = make_float2(lo, hi);
        }
    }
}

// =====================================================================
// Column softmax stats (softmax over t for each (bh, s)):
// online max + sum of exp, branchless. scores layout [z][t][s].
// =====================================================================
__global__ __launch_bounds__(256)
void softmax_stats(const float* __restrict__ S, float* __restrict__ Mv,
                   float* __restrict__ Lv)
{
    const int z = blockIdx.y;
    const int s = blockIdx.x * 256 + threadIdx.x;
    const float* p = S + (long long)z * (2048LL * 2048LL) + s;
    float m = -1e30f, l = 0.0f;
    for (int t = 0; t < 2048; t += 4) {
        float x0 = p[(long long)(t + 0) * 2048];
        float x1 = p[(long long)(t + 1) * 2048];
        float x2 = p[(long long)(t + 2) * 2048];
        float x3 = p[(long long)(t + 3) * 2048];
        float nm;
        nm = fmaxf(m, x0); l = l * __expf(m - nm) + __expf(x0 - nm); m = nm;
        nm = fmaxf(m, x1); l = l * __expf(m - nm) + __expf(x1 - nm); m = nm;
        nm = fmaxf(m, x2); l = l * __expf(m - nm) + __expf(x2 - nm); m = nm;
        nm = fmaxf(m, x3); l = l * __expf(m - nm) + __expf(x3 - nm); m = nm;
    }
    Mv[z * 2048 + s] = m;
    Lv[z * 2048 + s] = 1.0f / l;
}

// =====================================================================
// post[t,d] = sum_s exp(score[t,s]-m[s])*invl[s] * V[s,d]; epilogue
// gelu(x)/sqrt(S) scattered into ctx[token][h*64+d].
// BM=128, BN=64(=head_dim), BK=16, 256 threads, 8x4 per thread.
// =====================================================================
__global__ __launch_bounds__(256, 2)
void gemm_attnv(const float* __restrict__ Sc, const float* __restrict__ QKV,
                const float* __restrict__ Mv, const float* __restrict__ Lv,
                float* __restrict__ Ctx)
{
    const int z = blockIdx.z;
    const int b = z >> 4, h = z & 15;
    const float* A  = Sc  + (long long)z * (2048LL * 2048LL);
    const float* V  = QKV + (long long)b * (2048LL * 3072LL) + 2048 + h * 64;
    const float* mv = Mv + z * 2048;
    const float* lv = Lv + z * 2048;
    float*       C  = Ctx + (long long)b * (2048LL * 1024LL) + h * 64;

    __shared__ u64 As2[16][129];
    __shared__ __align__(16) float Bs[16][68];

    const int tid = threadIdx.x;
    const long long bm = (long long)blockIdx.y * 128;

    const int warp = tid >> 5, lane = tid & 31;
    const int tm = (warp >> 1) * 32 + (lane >> 3) * 8;   // 0..120
    const int tn = (warp & 1)  * 32 + (lane & 7)  * 4;   // 0..60
    const int tn2 = tn >> 1;

    const int lm0 = tid >> 2;
    const int lk  = (tid & 3) * 4;
    const float* Aload = A + (bm + lm0) * 2048 + lk;
    const int vRow = tid >> 4;              // 0..15
    const int vCol = (tid & 15) * 4;        // 0..60
    const float* Vload = V + (long long)vRow * 3072 + vCol;

    float4 pa0 = *(const float4*)(Aload);
    float4 pa1 = *(const float4*)(Aload + 64LL * 2048);
    float4 pm  = *(const float4*)(mv + lk);
    float4 pl  = *(const float4*)(lv + lk);
    float4 pv  = *(const float4*)(Vload);

    u64 acc[8][2];
    #pragma unroll
    for (int i = 0; i < 8; i++) { acc[i][0] = 0ULL; acc[i][1] = 0ULL; }

    for (int k0 = 0; k0 < 2048; k0 += 16) {
        As2[lk+0][lm0]    = dup2(__expf(pa0.x - pm.x) * pl.x);
        As2[lk+1][lm0]    = dup2(__expf(pa0.y - pm.y) * pl.y);
        As2[lk+2][lm0]    = dup2(__expf(pa0.z - pm.z) * pl.z);
        As2[lk+3][lm0]    = dup2(__expf(pa0.w - pm.w) * pl.w);
        As2[lk+0][lm0+64] = dup2(__expf(pa1.x - pm.x) * pl.x);
        As2[lk+1][lm0+64] = dup2(__expf(pa1.y - pm.y) * pl.y);
        As2[lk+2][lm0+64] = dup2(__expf(pa1.z - pm.z) * pl.z);
        As2[lk+3][lm0+64] = dup2(__expf(pa1.w - pm.w) * pl.w);
        *(float4*)(&Bs[vRow][vCol]) = pv;
        __syncthreads();

        if (k0 + 16 < 2048) {
            pa0 = *(const float4*)(Aload + (k0 + 16));
            pa1 = *(const float4*)(Aload + (k0 + 16) + 64LL * 2048);
            pm  = *(const float4*)(mv + (k0 + 16) + lk);
            pl  = *(const float4*)(lv + (k0 + 16) + lk);
            pv  = *(const float4*)(Vload + (long long)(k0 + 16) * 3072);
        }

        #pragma unroll
        for (int k = 0; k < 16; k++) {
            const u64* brow = (const u64*)(&Bs[k][0]);
            u64 ra[8];
            #pragma unroll
            for (int i = 0; i < 8; i++) ra[i] = As2[k][tm + i];
            u64 rb0 = brow[tn2], rb1 = brow[tn2 + 1];
            #pragma unroll
            for (int i = 0; i < 8; i++) {
                acc[i][0] = fma2(ra[i], rb0, acc[i][0]);
                acc[i][1] = fma2(ra[i], rb1, acc[i][1]);
            }
        }
        __syncthreads();
    }

    const float rs = 0.022097086912079608f;  // 1/sqrt(2048)
    #pragma unroll
    for (int i = 0; i < 8; i++) {
        float* crow = C + (bm + tm + i) * 1024 + tn;
        #pragma unroll
        for (int j = 0; j < 2; j++) {
            float lo = gelu_f(lo32(acc[i][j])) * rs;
            float hi = gelu_f(hi32(acc[i][j])) * rs;
            *(float2*)(crow + 2 * j) = make_float2(lo, hi);
        }
    }
}

// =====================================================================
// LayerNorm(x + y) * g + b   (row = 1024, one block per token row)
// =====================================================================
__global__ __launch_bounds__(256)
void ln_kernel(const float* __restrict__ X, const float* __restrict__ Y,
               const float* __restrict__ g, const float* __restrict__ be,
               float* __restrict__ O)
{
    const long long row = blockIdx.x;
    const int t = threadIdx.x;
    const float4 a = *(const float4*)(X + row * 1024 + t * 4);
    const float4 c = *(const float4*)(Y + row * 1024 + t * 4);
    float v0 = a.x + c.x, v1 = a.y + c.y, v2 = a.z + c.z, v3 = a.w + c.w;
    float s = v0 + v1 + v2 + v3;
    float q = v0 * v0 + v1 * v1 + v2 * v2 + v3 * v3;
    #pragma unroll
    for (int o = 16; o > 0; o >>= 1) {
        s += __shfl_xor_sync(0xffffffffu, s, o);
        q += __shfl_xor_sync(0xffffffffu, q, o);
    }
    __shared__ float ss[8], qq[8];
    const int w = t >> 5;
    if ((t & 31) == 0) { ss[w] = s; qq[w] = q; }
    __syncthreads();
    if (t < 32) {
        s = (t < 8) ? ss[t] : 0.0f;
        q = (t < 8) ? qq[t] : 0.0f;
        #pragma unroll
        for (int o = 4; o > 0; o >>= 1) {
            s += __shfl_xor_sync(0xffffffffu, s, o);
            q += __shfl_xor_sync(0xffffffffu, q, o);
        }
        if (t == 0) { ss[0] = s; qq[0] = q; }
    }
    __syncthreads();
    const float mu  = ss[0] * (1.0f / 1024.0f);
    const float var = qq[0] * (1.0f / 1024.0f) - mu * mu;
    const float r   = rsqrtf(var + 1e-5f);
    const float4 gg = *(const float4*)(g  + t * 4);
    const float4 bb = *(const float4*)(be + t * 4);
    float4 o4;
    o4.x = (v0 - mu) * r * gg.x + bb.x;
    o4.y = (v1 - mu) * r * gg.y + bb.y;
    o4.z = (v2 - mu) * r * gg.z + bb.z;
    o4.w = (v3 - mu) * r * gg.w + bb.w;
    *(float4*)(O + row * 1024 + t * 4) = o4;
}

// =====================================================================
// Host launcher (graph-capturable: kernel launches only)
// =====================================================================
extern "C" void kernel_launch(void* const* d_in, const int* in_sizes, int n_in,
                              void* d_out, int out_size)
{
    (void)in_sizes; (void)n_in; (void)out_size;
    const float* src  = (const float*)d_in[0];
    const float* ipw  = (const float*)d_in[1];
    const float* ipb  = (const float*)d_in[2];
    const float* outw = (const float*)d_in[3];
    const float* outb = (const float*)d_in[4];
    const float* l1w  = (const float*)d_in[5];
    const float* l1b  = (const float*)d_in[6];
    const float* l2w  = (const float*)d_in[7];
    const float* l2b  = (const float*)d_in[8];
    const float* g1   = (const float*)d_in[9];
    const float* b1   = (const float*)d_in[10];
    const float* g2   = (const float*)d_in[11];
    const float* b2   = (const float*)d_in[12];
    float* out = (float*)d_out;

    float *qkv, *sc, *mv, *lv, *ctx, *tmp, *x, *h1, *y;
    cudaGetSymbolAddress((void**)&qkv, g_qkv);
    cudaGetSymbolAddress((void**)&sc,  g_scores);
    cudaGetSymbolAddress((void**)&mv,  g_m);
    cudaGetSymbolAddress((void**)&lv,  g_linv);
    cudaGetSymbolAddress((void**)&ctx, g_ctx);
    cudaGetSymbolAddress((void**)&tmp, g_tmp);
    cudaGetSymbolAddress((void**)&x,   g_x);
    cudaGetSymbolAddress((void**)&h1,  g_h1);
    cudaGetSymbolAddress((void**)&y,   g_y);

    const dim3 T(256);

    // 1) qkv = src @ in_proj_w^T + in_proj_b     [4096, 3072]
    gemm_nt<1><<<dim3(24, 32, 1), T>>>(src, ipw, ipb, qkv,
        1024, 1024, 1024, 3072, 0, 0, 0, 0, 0, 0, 1, 1.0f);

    // 2) scores[bh][t][s] = (q_t . k_s) * 1/sqrt(64)   batched over 32 (b,h)
    gemm_nt<2><<<dim3(16, 16, 32), T>>>(qkv, qkv + 1024, nullptr, sc,
        64, 3072, 3072, 2048,
        6291456LL, 64LL,          // A: +b*2048*3072, +h*64
        6291456LL, 64LL,          // B: same (k base already +1024)
        67108864LL, 4194304LL,    // C: +b*16*2048^2, +h*2048^2
        16, 0.125f);

    // 3) column-softmax stats over t
    softmax_stats<<<dim3(8, 32), T>>>(sc, mv, lv);

    // 4) post = softmaxed(scores)^applied . V, gelu, /sqrt(S) -> ctx
    gemm_attnv<<<dim3(1, 16, 32), T>>>(sc, qkv, mv, lv, ctx);

    // 5) tmp = ctx @ out_w^T + out_b
    gemm_nt<1><<<dim3(8, 32, 1), T>>>(ctx, outw, outb, tmp,
        1024, 1024, 1024, 1024, 0, 0, 0, 0, 0, 0, 1, 1.0f);

    // 6) x = LN(src + tmp)
    ln_kernel<<<4096, T>>>(src, tmp, g1, b1, x);

    // 7) h1 = gelu(x @ lin1_w^T + lin1_b)        [4096, 4096]
    gemm_nt<3><<<dim3(32, 32, 1), T>>>(x, l1w, l1b, h1,
        1024, 1024, 1024, 4096, 0, 0, 0, 0, 0, 0, 1, 1.0f);

    // 8) y = h1 @ lin2_w^T + lin2_b              [4096, 1024]
    gemm_nt<1><<<dim3(8, 32, 1), T>>>(h1, l2w, l2b, y,
        4096, 4096, 4096, 1024, 0, 0, 0, 0, 0, 0, 1, 1.0f);

    // 9) out = LN(x + y)
    ln_kernel<<<4096, T>>>(x, y, g2, b2, out);
}